// round 4
// baseline (speedup 1.0000x reference)
#include <cuda_runtime.h>
#include <cstdint>
#include <math.h>

#define NC 16       // components
#define NDIM 16     // dimension
#define NL 6        // flow steps

// ---------------------------------------------------------------------------
// Device globals (setup kernel -> main kernel). No dynamic allocation.
// ---------------------------------------------------------------------------
__device__ float g_P[NC * NDIM * NDIM];   // L^{-1} per component, zeros above diag
__device__ float g_base[NC];              // -0.5*DIM*log(2pi) - half_logdet
__device__ float g_alpha_flat[NL * NC];   // exp(log_alpha)

// ---------------------------------------------------------------------------
// Packed f32x2 helpers (Blackwell FFMA2 path — ptxas won't auto-fuse)
// ---------------------------------------------------------------------------
union F2U { float2 f; unsigned long long u; };

__device__ __forceinline__ float2 add2(float2 a, float2 b) {
    F2U A, B, R; A.f = a; B.f = b;
    asm("add.rn.f32x2 %0, %1, %2;" : "=l"(R.u) : "l"(A.u), "l"(B.u));
    return R.f;
}
__device__ __forceinline__ float2 mul2(float2 a, float2 b) {
    F2U A, B, R; A.f = a; B.f = b;
    asm("mul.rn.f32x2 %0, %1, %2;" : "=l"(R.u) : "l"(A.u), "l"(B.u));
    return R.f;
}
__device__ __forceinline__ float2 fma2(float2 a, float2 b, float2 c) {
    F2U A, B, Cc, R; A.f = a; B.f = b; Cc.f = c;
    asm("fma.rn.f32x2 %0, %1, %2, %3;" : "=l"(R.u) : "l"(A.u), "l"(B.u), "l"(Cc.u));
    return R.f;
}

// ---------------------------------------------------------------------------
// Setup: per-component Cholesky of cov, P = L^{-1} (diag folded), half_logdet,
// alpha = exp(log_alpha). One block, (16,16) threads: x = row i, y = component.
// Runs every launch (deterministic); cost ~2-4 us.
// ---------------------------------------------------------------------------
__global__ void setup_kernel(const float* __restrict__ log_alpha,
                             const float* __restrict__ cov) {
    const int i = threadIdx.x;   // row
    const int c = threadIdx.y;   // component

    __shared__ float scol[NC][NDIM];
    __shared__ float sL[NC][NDIM][NDIM];

    // Each thread holds row i of cov[c]
    float a[NDIM];
#pragma unroll
    for (int j = 0; j < NDIM; j++) a[j] = cov[(c * NDIM + i) * NDIM + j];

    float Lrow[NDIM];
#pragma unroll
    for (int k = 0; k < NDIM; k++) {
        if (i == k) scol[c][k] = sqrtf(a[k]);
        __syncthreads();
        float lkk = scol[c][k];
        if (i > k) scol[c][i] = a[k] / lkk;
        __syncthreads();
        float lik = (i >= k) ? scol[c][i] : 0.0f;
        Lrow[k] = lik;
        float upd = (i > k) ? lik : 0.0f;
#pragma unroll
        for (int j = 0; j < NDIM; j++) {
            if (j > k) a[j] -= upd * scol[c][j];
        }
        __syncthreads();
    }
#pragma unroll
    for (int k = 0; k < NDIM; k++) sL[c][i][k] = Lrow[k];
    __syncthreads();

    // Thread i computes column i of P = L^{-1} (forward substitution on e_i).
    // For r < i the solution is exactly 0, giving the zero upper triangle.
    {
        float x[NDIM];
#pragma unroll
        for (int r = 0; r < NDIM; r++) {
            float s = (r == i) ? 1.0f : 0.0f;
#pragma unroll
            for (int m = 0; m < NDIM; m++) {
                if (m < r) s -= sL[c][r][m] * x[m];
            }
            x[r] = s / sL[c][r][r];
            g_P[(c * NDIM + r) * NDIM + i] = x[r];
        }
    }

    if (i == 0) {
        float hld = 0.0f;
#pragma unroll
        for (int d = 0; d < NDIM; d++) hld += logf(sL[c][d][d]);
        // -0.5 * DIM * log(2*pi) = -8 * log(2*pi)
        g_base[c] = -8.0f * 1.83787706640934548356f - hld;
    }

    int t = c * NDIM + i;
    if (t < NL * NC) g_alpha_flat[t] = expf(log_alpha[t]);
}

// ---------------------------------------------------------------------------
// Main kernel: block = 256 threads = 64 points x 4 component-groups.
// All lanes of a warp share the component -> every shared read is a broadcast.
// ---------------------------------------------------------------------------
__global__ void __launch_bounds__(256, 2)
density_kernel(const float* __restrict__ z,
               const float* __restrict__ z0,
               const float* __restrict__ beta_g,
               const float* __restrict__ mean,
               float* __restrict__ out,
               int N)
{
    __shared__ __align__(16) float s_nz0[NL * NC * NDIM];   // -z0
    __shared__ __align__(16) float s_P[NC * NDIM * NDIM];   // L^{-1}
    __shared__ __align__(16) float s_nmean[NC * NDIM];      // -mean
    __shared__ float s_alpha[NL * NC];
    __shared__ float s_beta[NL * NC];
    __shared__ float s_base[NC];

    const int tid = threadIdx.x;
    for (int t = tid; t < NL * NC * NDIM; t += 256) s_nz0[t] = -z0[t];
    for (int t = tid; t < NC * NDIM * NDIM; t += 256) s_P[t] = g_P[t];
    for (int t = tid; t < NC * NDIM; t += 256) s_nmean[t] = -mean[t];
    if (tid < NL * NC) { s_alpha[tid] = g_alpha_flat[tid]; s_beta[tid] = beta_g[tid]; }
    if (tid < NC) s_base[tid] = g_base[tid];
    __syncthreads();

    const int cg = tid >> 6;                       // warp-uniform component group
    const int n  = blockIdx.x * 64 + (tid & 63);
    if (n >= N) return;

    // Load z[n] into 8 packed float2 registers (4x LDG.128, coalesced)
    float2 zr[8];
    const float4* zp = reinterpret_cast<const float4*>(z + (size_t)n * NDIM);
#pragma unroll
    for (int q4 = 0; q4 < 4; q4++) {
        float4 v = zp[q4];
        zr[q4 * 2 + 0] = make_float2(v.x, v.y);
        zr[q4 * 2 + 1] = make_float2(v.z, v.w);
    }

    float vout[4];
#pragma unroll
    for (int ci = 0; ci < 4; ci++) {
        const int c = cg * 4 + ci;

        float2 zc[8];
#pragma unroll
        for (int j = 0; j < 8; j++) zc[j] = zr[j];
        float slj = 0.0f;

        // ---- 6 radial flow steps ----
#pragma unroll
        for (int l = 0; l < NL; l++) {
            const float4* nz4 =
                reinterpret_cast<const float4*>(&s_nz0[(l * NC + c) * NDIM]);
            float2 d[8];
            float2 acc0, acc1;
            {
                float4 v = nz4[0];
                d[0] = add2(zc[0], make_float2(v.x, v.y));
                d[1] = add2(zc[1], make_float2(v.z, v.w));
                acc0 = mul2(d[0], d[0]);
                acc1 = mul2(d[1], d[1]);
            }
#pragma unroll
            for (int q4 = 1; q4 < 4; q4++) {
                float4 v = nz4[q4];
                d[q4 * 2 + 0] = add2(zc[q4 * 2 + 0], make_float2(v.x, v.y));
                d[q4 * 2 + 1] = add2(zc[q4 * 2 + 1], make_float2(v.z, v.w));
                acc0 = fma2(d[q4 * 2 + 0], d[q4 * 2 + 0], acc0);
                acc1 = fma2(d[q4 * 2 + 1], d[q4 * 2 + 1], acc1);
            }
            acc0 = add2(acc0, acc1);
            float r2 = acc0.x + acc0.y;
            float r  = r2 * rsqrtf(r2);               // MUFU.RSQ + mul
            float alpha = s_alpha[l * NC + c];
            float beta  = s_beta[l * NC + c];
            float h  = __fdividef(1.0f, alpha + r);   // MUFU.RCP
            float bh = beta * h;
            float rh = r * h;
            float2 bb = make_float2(bh, bh);
#pragma unroll
            for (int j = 0; j < 8; j++) zc[j] = fma2(d[j], bb, zc[j]);
            // log_det = 15*log1p(bh) + log1p(bh*(1-rh))
            float l1 = __logf(1.0f + bh);
            float l2 = __logf(fmaf(bh, 1.0f - rh, 1.0f));
            slj = fmaf(15.0f, l1, slj) + l2;
        }

        // ---- diff = zk - mean ----
        const float4* nm4 = reinterpret_cast<const float4*>(&s_nmean[c * NDIM]);
#pragma unroll
        for (int q4 = 0; q4 < 4; q4++) {
            float4 v = nm4[q4];
            zc[q4 * 2 + 0] = add2(zc[q4 * 2 + 0], make_float2(v.x, v.y));
            zc[q4 * 2 + 1] = add2(zc[q4 * 2 + 1], make_float2(v.z, v.w));
        }

        // ---- q = || L^{-1} diff ||^2 : triangular packed matvec ----
        float q = 0.0f;
        const float4* P4 = reinterpret_cast<const float4*>(&s_P[c * NDIM * NDIM]);
#pragma unroll
        for (int i = 0; i < NDIM; i++) {
            const int nq = i / 4 + 1;   // quads covering pair idx <= i/2 (rest are zeros)
            float2 acc = make_float2(0.0f, 0.0f);
#pragma unroll
            for (int w = 0; w < 4; w++) {
                if (w < nq) {
                    float4 p = P4[i * 4 + w];
                    acc = fma2(make_float2(p.x, p.y), zc[w * 2 + 0], acc);
                    acc = fma2(make_float2(p.z, p.w), zc[w * 2 + 1], acc);
                }
            }
            float sol = acc.x + acc.y;
            q = fmaf(sol, sol, q);
        }

        float v = fmaf(q, -0.5f, s_base[c]) + slj;
        if (isnan(v)) v = __int_as_float(0xff800000);   // -inf, matching reference
        vout[ci] = v;
    }

    // Coalesced-ish 16B store: out[n][cg*4 .. cg*4+3]
    float4* op = reinterpret_cast<float4*>(out + (size_t)n * NC + cg * 4);
    *op = make_float4(vout[0], vout[1], vout[2], vout[3]);
}

// ---------------------------------------------------------------------------
// Launch contract
// ---------------------------------------------------------------------------
extern "C" void kernel_launch(void* const* d_in, const int* in_sizes, int n_in,
                              void* d_out, int out_size) {
    const float* z    = (const float*)d_in[0];   // (N, 16)
    const float* z0   = (const float*)d_in[1];   // (6, 16, 16)
    const float* la   = (const float*)d_in[2];   // (6, 16)
    const float* beta = (const float*)d_in[3];   // (6, 16)
    const float* mean = (const float*)d_in[4];   // (16, 16)... (C, DIM)
    const float* cov  = (const float*)d_in[5];   // (16, 16, 16)
    float* out = (float*)d_out;                  // (N, 16) float32

    const int N = in_sizes[0] / NDIM;

    setup_kernel<<<1, dim3(NDIM, NC)>>>(la, cov);
    const int blocks = (N + 63) / 64;
    density_kernel<<<blocks, 256>>>(z, z0, beta, mean, out, N);
}

// round 5
// speedup vs baseline: 1.0129x; 1.0129x over previous
#include <cuda_runtime.h>
#include <cstdint>
#include <math.h>

#define NC 16       // components
#define NDIM 16     // dimension
#define NL 6        // flow steps

// ---------------------------------------------------------------------------
// Device globals (setup kernel -> main kernel). No dynamic allocation.
// ---------------------------------------------------------------------------
__device__ float g_P[NC * NDIM * NDIM];   // L^{-1} per component, zeros above diag
__device__ float g_base[NC];              // -0.5*DIM*log(2pi) - half_logdet
__device__ float g_alpha_flat[NL * NC];   // exp(log_alpha)

// ---------------------------------------------------------------------------
// Packed f32x2 helpers operating on raw 64-bit pairs (no float2 unions ->
// no pack/unpack MOV traffic around every asm block).
// ---------------------------------------------------------------------------
typedef unsigned long long u64;

__device__ __forceinline__ u64 add2(u64 a, u64 b) {
    u64 r; asm("add.rn.f32x2 %0, %1, %2;" : "=l"(r) : "l"(a), "l"(b)); return r;
}
__device__ __forceinline__ u64 mul2(u64 a, u64 b) {
    u64 r; asm("mul.rn.f32x2 %0, %1, %2;" : "=l"(r) : "l"(a), "l"(b)); return r;
}
__device__ __forceinline__ u64 fma2(u64 a, u64 b, u64 c) {
    u64 r; asm("fma.rn.f32x2 %0, %1, %2, %3;" : "=l"(r) : "l"(a), "l"(b), "l"(c)); return r;
}
__device__ __forceinline__ u64 bcast2(float x) {
    u64 r; asm("mov.b64 %0, {%1, %1};" : "=l"(r) : "f"(x)); return r;
}
__device__ __forceinline__ float hsum2(u64 a) {
    float x, y; asm("mov.b64 {%0, %1}, %2;" : "=f"(x), "=f"(y) : "l"(a));
    return x + y;
}

// ---------------------------------------------------------------------------
// Setup: per-component Cholesky of cov, P = L^{-1} (diag folded), half_logdet,
// alpha = exp(log_alpha). One block, (16,16) threads: x = row i, y = component.
// ---------------------------------------------------------------------------
__global__ void setup_kernel(const float* __restrict__ log_alpha,
                             const float* __restrict__ cov) {
    const int i = threadIdx.x;   // row
    const int c = threadIdx.y;   // component

    __shared__ float scol[NC][NDIM];
    __shared__ float sL[NC][NDIM][NDIM];

    float a[NDIM];
#pragma unroll
    for (int j = 0; j < NDIM; j++) a[j] = cov[(c * NDIM + i) * NDIM + j];

    float Lrow[NDIM];
#pragma unroll
    for (int k = 0; k < NDIM; k++) {
        if (i == k) scol[c][k] = sqrtf(a[k]);
        __syncthreads();
        float lkk = scol[c][k];
        if (i > k) scol[c][i] = a[k] / lkk;
        __syncthreads();
        float lik = (i >= k) ? scol[c][i] : 0.0f;
        Lrow[k] = lik;
        float upd = (i > k) ? lik : 0.0f;
#pragma unroll
        for (int j = 0; j < NDIM; j++) {
            if (j > k) a[j] -= upd * scol[c][j];
        }
        __syncthreads();
    }
#pragma unroll
    for (int k = 0; k < NDIM; k++) sL[c][i][k] = Lrow[k];
    __syncthreads();

    // Thread i computes column i of P = L^{-1} (forward substitution on e_i).
    // For r < i the solution is exactly 0 -> zero upper triangle.
    {
        float x[NDIM];
#pragma unroll
        for (int r = 0; r < NDIM; r++) {
            float s = (r == i) ? 1.0f : 0.0f;
#pragma unroll
            for (int m = 0; m < NDIM; m++) {
                if (m < r) s -= sL[c][r][m] * x[m];
            }
            x[r] = s / sL[c][r][r];
            g_P[(c * NDIM + r) * NDIM + i] = x[r];
        }
    }

    if (i == 0) {
        float hld = 0.0f;
#pragma unroll
        for (int d = 0; d < NDIM; d++) hld += logf(sL[c][d][d]);
        g_base[c] = -8.0f * 1.83787706640934548356f - hld;   // -0.5*16*log(2pi) - hld
    }

    int t = c * NDIM + i;
    if (t < NL * NC) g_alpha_flat[t] = expf(log_alpha[t]);
}

// ---------------------------------------------------------------------------
// Main kernel: block = 256 threads = 64 points x 4 component-groups.
// All lanes of a warp share the component -> every shared read is a broadcast.
// All vector state lives in u64 packed pairs; loads come in as ulonglong2.
// ---------------------------------------------------------------------------
__global__ void __launch_bounds__(256, 2)
density_kernel(const float* __restrict__ z,
               const float* __restrict__ z0,
               const float* __restrict__ beta_g,
               const float* __restrict__ mean,
               float* __restrict__ out,
               int N)
{
    __shared__ __align__(16) float s_nz0[NL * NC * NDIM];   // -z0
    __shared__ __align__(16) float s_P[NC * NDIM * NDIM];   // L^{-1}
    __shared__ __align__(16) float s_nmean[NC * NDIM];      // -mean
    __shared__ float s_alpha[NL * NC];
    __shared__ float s_beta[NL * NC];
    __shared__ float s_base[NC];

    const int tid = threadIdx.x;
    for (int t = tid; t < NL * NC * NDIM; t += 256) s_nz0[t] = -z0[t];
    for (int t = tid; t < NC * NDIM * NDIM; t += 256) s_P[t] = g_P[t];
    for (int t = tid; t < NC * NDIM; t += 256) s_nmean[t] = -mean[t];
    if (tid < NL * NC) { s_alpha[tid] = g_alpha_flat[tid]; s_beta[tid] = beta_g[tid]; }
    if (tid < NC) s_base[tid] = g_base[tid];
    __syncthreads();

    const int cg = tid >> 6;                       // warp-uniform component group
    const int n  = blockIdx.x * 64 + (tid & 63);
    if (n >= N) return;

    // Load z[n] as 4x LDG.128 -> 8 packed pairs, no repacking.
    u64 zr[8];
    {
        const ulonglong2* zp = reinterpret_cast<const ulonglong2*>(z + (size_t)n * NDIM);
#pragma unroll
        for (int q = 0; q < 4; q++) {
            ulonglong2 v = zp[q];
            zr[q * 2 + 0] = v.x;
            zr[q * 2 + 1] = v.y;
        }
    }

    float vout[4];
#pragma unroll
    for (int ci = 0; ci < 4; ci++) {
        const int c = cg * 4 + ci;

        u64 zc[8];
#pragma unroll
        for (int j = 0; j < 8; j++) zc[j] = zr[j];
        float slj = 0.0f;

        // ---- 6 radial flow steps ----
#pragma unroll
        for (int l = 0; l < NL; l++) {
            const ulonglong2* nz2 =
                reinterpret_cast<const ulonglong2*>(&s_nz0[(l * NC + c) * NDIM]);
            u64 d[8], acc0, acc1;
            {
                ulonglong2 v0 = nz2[0];
                ulonglong2 v1 = nz2[1];
                d[0] = add2(zc[0], v0.x);
                d[1] = add2(zc[1], v0.y);
                d[2] = add2(zc[2], v1.x);
                d[3] = add2(zc[3], v1.y);
                acc0 = mul2(d[0], d[0]);
                acc1 = mul2(d[1], d[1]);
                acc0 = fma2(d[2], d[2], acc0);
                acc1 = fma2(d[3], d[3], acc1);
                ulonglong2 v2 = nz2[2];
                ulonglong2 v3 = nz2[3];
                d[4] = add2(zc[4], v2.x);
                d[5] = add2(zc[5], v2.y);
                d[6] = add2(zc[6], v3.x);
                d[7] = add2(zc[7], v3.y);
                acc0 = fma2(d[4], d[4], acc0);
                acc1 = fma2(d[5], d[5], acc1);
                acc0 = fma2(d[6], d[6], acc0);
                acc1 = fma2(d[7], d[7], acc1);
            }
            float r2 = hsum2(add2(acc0, acc1));
            float r  = r2 * rsqrtf(r2);               // MUFU.RSQ + mul
            float alpha = s_alpha[l * NC + c];
            float beta  = s_beta[l * NC + c];
            float h  = __fdividef(1.0f, alpha + r);   // MUFU.RCP
            float bh = beta * h;
            float rh = r * h;
            u64 bb = bcast2(bh);
#pragma unroll
            for (int j = 0; j < 8; j++) zc[j] = fma2(d[j], bb, zc[j]);
            // log_det = 15*log1p(bh) + log1p(bh - bh*rh)
            float t1 = 1.0f + bh;
            float l1 = __logf(t1);
            float l2 = __logf(fmaf(-bh, rh, t1));
            slj = fmaf(15.0f, l1, slj) + l2;
        }

        // ---- diff = zk - mean ----
        {
            const ulonglong2* nm2 =
                reinterpret_cast<const ulonglong2*>(&s_nmean[c * NDIM]);
#pragma unroll
            for (int q = 0; q < 4; q++) {
                ulonglong2 v = nm2[q];
                zc[q * 2 + 0] = add2(zc[q * 2 + 0], v.x);
                zc[q * 2 + 1] = add2(zc[q * 2 + 1], v.y);
            }
        }

        // ---- q = || L^{-1} diff ||^2 : triangular packed matvec ----
        float q = 0.0f;
        const ulonglong2* P2 =
            reinterpret_cast<const ulonglong2*>(&s_P[c * NDIM * NDIM]);
#pragma unroll
        for (int i = 0; i < NDIM; i++) {
            const int nq = i / 4 + 1;   // 16B-quads covering cols <= i (rest zero)
            u64 acc;
            {
                ulonglong2 p = P2[i * 4 + 0];
                acc = mul2(p.x, zc[0]);
                acc = fma2(p.y, zc[1], acc);
            }
#pragma unroll
            for (int w = 1; w < 4; w++) {
                if (w < nq) {
                    ulonglong2 p = P2[i * 4 + w];
                    acc = fma2(p.x, zc[w * 2 + 0], acc);
                    acc = fma2(p.y, zc[w * 2 + 1], acc);
                }
            }
            float sol = hsum2(acc);
            q = fmaf(sol, sol, q);
        }

        float v = fmaf(q, -0.5f, s_base[c]) + slj;
        if (isnan(v)) v = __int_as_float(0xff800000);   // -inf, matching reference
        vout[ci] = v;
    }

    // 16B store: out[n][cg*4 .. cg*4+3]
    float4* op = reinterpret_cast<float4*>(out + (size_t)n * NC + cg * 4);
    *op = make_float4(vout[0], vout[1], vout[2], vout[3]);
}

// ---------------------------------------------------------------------------
// Launch contract
// ---------------------------------------------------------------------------
extern "C" void kernel_launch(void* const* d_in, const int* in_sizes, int n_in,
                              void* d_out, int out_size) {
    const float* z    = (const float*)d_in[0];   // (N, 16)
    const float* z0   = (const float*)d_in[1];   // (6, 16, 16)
    const float* la   = (const float*)d_in[2];   // (6, 16)
    const float* beta = (const float*)d_in[3];   // (6, 16)
    const float* mean = (const float*)d_in[4];   // (16, 16)
    const float* cov  = (const float*)d_in[5];   // (16, 16, 16)
    float* out = (float*)d_out;                  // (N, 16) float32

    const int N = in_sizes[0] / NDIM;

    setup_kernel<<<1, dim3(NDIM, NC)>>>(la, cov);
    const int blocks = (N + 63) / 64;
    density_kernel<<<blocks, 256>>>(z, z0, beta, mean, out, N);
}

// round 7
// speedup vs baseline: 1.3140x; 1.2973x over previous
#include <cuda_runtime.h>
#include <cstdint>
#include <math.h>

#define NC 16       // components
#define NDIM 16     // dimension
#define NL 6        // flow steps

// ---------------------------------------------------------------------------
// Device globals (setup kernel -> main kernel). No dynamic allocation.
// ---------------------------------------------------------------------------
__device__ float g_P[NC * NDIM * NDIM];    // L^{-1} per component (zeros above diag)
__device__ float g_base[NC];               // -0.5*DIM*log(2pi) - half_logdet
__device__ float g_alpha_flat[NL * NC];    // exp(log_alpha)
__device__ float g_e[NC * NL * NDIM];      // [c][l][i]: l<5: z0_l - z0_{l+1}; l=5: z0_5
__device__ float g_nz00[NC * NDIM];        // -z0_0
__device__ int   g_flag;                   // 1 if P==I for all c and mean==0

// ---------------------------------------------------------------------------
// Packed f32x2 helpers on raw 64-bit pairs.
// ---------------------------------------------------------------------------
typedef unsigned long long u64;

__device__ __forceinline__ u64 add2(u64 a, u64 b) {
    u64 r; asm("add.rn.f32x2 %0, %1, %2;" : "=l"(r) : "l"(a), "l"(b)); return r;
}
__device__ __forceinline__ u64 mul2(u64 a, u64 b) {
    u64 r; asm("mul.rn.f32x2 %0, %1, %2;" : "=l"(r) : "l"(a), "l"(b)); return r;
}
__device__ __forceinline__ u64 fma2(u64 a, u64 b, u64 c) {
    u64 r; asm("fma.rn.f32x2 %0, %1, %2, %3;" : "=l"(r) : "l"(a), "l"(b), "l"(c)); return r;
}
__device__ __forceinline__ u64 bcast2(float x) {
    u64 r; asm("mov.b64 %0, {%1, %1};" : "=l"(r) : "f"(x)); return r;
}
__device__ __forceinline__ float hsum2(u64 a) {
    float x, y; asm("mov.b64 {%0, %1}, %2;" : "=f"(x), "=f"(y) : "l"(a));
    return x + y;
}

// ---------------------------------------------------------------------------
// Setup: Cholesky -> P = L^{-1}, base, alpha=exp(log_alpha), flow deltas e,
// and the fast-path flag (P exactly identity AND mean exactly zero).
// One block, (16,16): x = row/element i, y = component c.
// ---------------------------------------------------------------------------
__global__ void setup_kernel(const float* __restrict__ log_alpha,
                             const float* __restrict__ cov,
                             const float* __restrict__ z0,
                             const float* __restrict__ mean) {
    const int i = threadIdx.x;   // row / element
    const int c = threadIdx.y;   // component

    __shared__ float scol[NC][NDIM];
    __shared__ float sL[NC][NDIM][NDIM];

    float a[NDIM];
#pragma unroll
    for (int j = 0; j < NDIM; j++) a[j] = cov[(c * NDIM + i) * NDIM + j];

    float Lrow[NDIM];
#pragma unroll
    for (int k = 0; k < NDIM; k++) {
        if (i == k) scol[c][k] = sqrtf(a[k]);
        __syncthreads();
        float lkk = scol[c][k];
        if (i > k) scol[c][i] = a[k] / lkk;
        __syncthreads();
        float lik = (i >= k) ? scol[c][i] : 0.0f;
        Lrow[k] = lik;
        float upd = (i > k) ? lik : 0.0f;
#pragma unroll
        for (int j = 0; j < NDIM; j++) {
            if (j > k) a[j] -= upd * scol[c][j];
        }
        __syncthreads();
    }
#pragma unroll
    for (int k = 0; k < NDIM; k++) sL[c][i][k] = Lrow[k];
    __syncthreads();

    // Thread i computes column i of P = L^{-1} (forward substitution on e_i).
    bool ok = true;
    {
        float x[NDIM];
#pragma unroll
        for (int r = 0; r < NDIM; r++) {
            float s = (r == i) ? 1.0f : 0.0f;
#pragma unroll
            for (int m = 0; m < NDIM; m++) {
                if (m < r) s -= sL[c][r][m] * x[m];
            }
            x[r] = s / sL[c][r][r];
            g_P[(c * NDIM + r) * NDIM + i] = x[r];
            ok = ok && (x[r] == ((r == i) ? 1.0f : 0.0f));
        }
    }
    ok = ok && (mean[c * NDIM + i] == 0.0f);

    if (i == 0) {
        float hld = 0.0f;
#pragma unroll
        for (int d = 0; d < NDIM; d++) hld += logf(sL[c][d][d]);
        g_base[c] = -8.0f * 1.83787706640934548356f - hld;
    }

    // Flow precompute: e[c][l][i]
#pragma unroll
    for (int l = 0; l < NL - 1; l++) {
        g_e[c * (NL * NDIM) + l * NDIM + i] =
            z0[(l * NC + c) * NDIM + i] - z0[((l + 1) * NC + c) * NDIM + i];
    }
    g_e[c * (NL * NDIM) + (NL - 1) * NDIM + i] = z0[((NL - 1) * NC + c) * NDIM + i];
    g_nz00[c * NDIM + i] = -z0[(0 * NC + c) * NDIM + i];

    int t = c * NDIM + i;
    if (t < NL * NC) g_alpha_flat[t] = expf(log_alpha[t]);

    int all = __syncthreads_and(ok ? 1 : 0);
    if (t == 0) g_flag = all;
}

// ---------------------------------------------------------------------------
// Main kernel: block = 512 threads = 16 warps; warp w -> component w,
// lanes -> 32 consecutive points. All shared reads are warp-uniform broadcasts.
// ---------------------------------------------------------------------------
__global__ void __launch_bounds__(512, 2)
density_kernel(const float* __restrict__ z,
               const float* __restrict__ z0,
               const float* __restrict__ beta_g,
               const float* __restrict__ mean,
               float* __restrict__ out,
               int N)
{
    __shared__ __align__(16) float s_e[NC * NL * NDIM];      // fast-path deltas
    __shared__ __align__(16) float s_nz00[NC * NDIM];        // -z0_0
    __shared__ __align__(16) float s_nz0all[NL * NC * NDIM]; // general path: -z0 (all l)
    __shared__ __align__(16) float s_P[NC * NDIM * NDIM];    // general path
    __shared__ __align__(16) float s_nmean[NC * NDIM];       // general path
    __shared__ float s_alpha[NL * NC];
    __shared__ float s_beta[NL * NC];
    __shared__ float s_base[NC];
    __shared__ float s_res[32 * 17];                         // [point][comp], pitch 17

    const int tid = threadIdx.x;
    const int flag = g_flag;

    for (int t = tid; t < NC * NL * NDIM; t += 512) s_e[t] = g_e[t];
    if (tid < NC * NDIM) s_nz00[tid] = g_nz00[tid];
    if (tid < NL * NC) { s_alpha[tid] = g_alpha_flat[tid]; s_beta[tid] = beta_g[tid]; }
    if (tid < NC) s_base[tid] = g_base[tid];
    if (!flag) {
        for (int t = tid; t < NL * NC * NDIM; t += 512) s_nz0all[t] = -z0[t];
        for (int t = tid; t < NC * NDIM * NDIM; t += 512) s_P[t] = g_P[t];
        if (tid < NC * NDIM) s_nmean[tid] = -mean[tid];
    }
    __syncthreads();

    const int c    = tid >> 5;          // warp-uniform component
    const int lane = tid & 31;          // point within group
    const int n    = blockIdx.x * 32 + lane;
    const int nn   = (n < N) ? n : 0;   // clamp: no divergence, store is guarded

    float v;   // result for (nn, c)

    if (flag) {
        // ================= FAST PATH: cov = I, mean = 0 =================
        // d_0 = z - z0_0 ; d_{l+1} = (1+bh_l) d_l + e_l ; d after l=5 is z_K.
        u64 d[8];
        {
            const ulonglong2* zp  = reinterpret_cast<const ulonglong2*>(z + (size_t)nn * NDIM);
            const ulonglong2* z00 = reinterpret_cast<const ulonglong2*>(&s_nz00[c * NDIM]);
#pragma unroll
            for (int q = 0; q < 4; q++) {
                ulonglong2 a = zp[q];
                ulonglong2 b = z00[q];
                d[q * 2 + 0] = add2(a.x, b.x);
                d[q * 2 + 1] = add2(a.y, b.y);
            }
        }

        const ulonglong2* e2 = reinterpret_cast<const ulonglong2*>(&s_e[c * (NL * NDIM)]);
        float p15 = 1.0f, pg = 1.0f;
#pragma unroll
        for (int l = 0; l < NL; l++) {
            u64 a0 = mul2(d[0], d[0]);
            u64 a1 = mul2(d[1], d[1]);
            a0 = fma2(d[2], d[2], a0);
            a1 = fma2(d[3], d[3], a1);
            a0 = fma2(d[4], d[4], a0);
            a1 = fma2(d[5], d[5], a1);
            a0 = fma2(d[6], d[6], a0);
            a1 = fma2(d[7], d[7], a1);
            float r2 = hsum2(add2(a0, a1));
            float r  = r2 * rsqrtf(r2);                 // MUFU.RSQ
            float alpha = s_alpha[l * NC + c];
            float beta  = s_beta[l * NC + c];
            float h  = __fdividef(1.0f, alpha + r);     // MUFU.RCP
            float bh = beta * h;
            float rh = r * h;
            float t1 = 1.0f + bh;
            p15 *= t1;
            pg  *= fmaf(-bh, rh, t1);                   // 1 + bh(1-rh)
            u64 tb = bcast2(t1);
            ulonglong2 ea = e2[l * 4 + 0];
            ulonglong2 eb = e2[l * 4 + 1];
            ulonglong2 ec = e2[l * 4 + 2];
            ulonglong2 ed = e2[l * 4 + 3];
            d[0] = fma2(d[0], tb, ea.x);
            d[1] = fma2(d[1], tb, ea.y);
            d[2] = fma2(d[2], tb, eb.x);
            d[3] = fma2(d[3], tb, eb.y);
            d[4] = fma2(d[4], tb, ec.x);
            d[5] = fma2(d[5], tb, ec.y);
            d[6] = fma2(d[6], tb, ed.x);
            d[7] = fma2(d[7], tb, ed.y);
        }
        float slj = fmaf(15.0f, __logf(p15), __logf(pg));

        // q = |z_K|^2  (mean = 0, P = I)
        u64 q0 = mul2(d[0], d[0]);
        u64 q1 = mul2(d[1], d[1]);
        q0 = fma2(d[2], d[2], q0);
        q1 = fma2(d[3], d[3], q1);
        q0 = fma2(d[4], d[4], q0);
        q1 = fma2(d[5], d[5], q1);
        q0 = fma2(d[6], d[6], q0);
        q1 = fma2(d[7], d[7], q1);
        float q = hsum2(add2(q0, q1));

        v = fmaf(q, -0.5f, s_base[c]) + slj;
    } else {
        // ================= GENERAL PATH (arbitrary cov/mean) =================
        u64 zc[8];
        {
            const ulonglong2* zp = reinterpret_cast<const ulonglong2*>(z + (size_t)nn * NDIM);
#pragma unroll
            for (int q = 0; q < 4; q++) {
                ulonglong2 a = zp[q];
                zc[q * 2 + 0] = a.x;
                zc[q * 2 + 1] = a.y;
            }
        }
        float slj = 0.0f;
#pragma unroll
        for (int l = 0; l < NL; l++) {
            const ulonglong2* nz2 =
                reinterpret_cast<const ulonglong2*>(&s_nz0all[(l * NC + c) * NDIM]);
            u64 d[8], acc0, acc1;
            {
                ulonglong2 v0 = nz2[0], v1 = nz2[1];
                d[0] = add2(zc[0], v0.x);
                d[1] = add2(zc[1], v0.y);
                d[2] = add2(zc[2], v1.x);
                d[3] = add2(zc[3], v1.y);
                acc0 = mul2(d[0], d[0]);
                acc1 = mul2(d[1], d[1]);
                acc0 = fma2(d[2], d[2], acc0);
                acc1 = fma2(d[3], d[3], acc1);
                ulonglong2 v2 = nz2[2], v3 = nz2[3];
                d[4] = add2(zc[4], v2.x);
                d[5] = add2(zc[5], v2.y);
                d[6] = add2(zc[6], v3.x);
                d[7] = add2(zc[7], v3.y);
                acc0 = fma2(d[4], d[4], acc0);
                acc1 = fma2(d[5], d[5], acc1);
                acc0 = fma2(d[6], d[6], acc0);
                acc1 = fma2(d[7], d[7], acc1);
            }
            float r2 = hsum2(add2(acc0, acc1));
            float r  = r2 * rsqrtf(r2);
            float alpha = s_alpha[l * NC + c];
            float beta  = s_beta[l * NC + c];
            float h  = __fdividef(1.0f, alpha + r);
            float bh = beta * h;
            float rh = r * h;
            u64 bb = bcast2(bh);
#pragma unroll
            for (int j = 0; j < 8; j++) zc[j] = fma2(d[j], bb, zc[j]);
            float t1 = 1.0f + bh;
            slj = fmaf(15.0f, __logf(t1), slj) + __logf(fmaf(-bh, rh, t1));
        }
        {
            const ulonglong2* nm2 =
                reinterpret_cast<const ulonglong2*>(&s_nmean[c * NDIM]);
#pragma unroll
            for (int q = 0; q < 4; q++) {
                ulonglong2 m = nm2[q];
                zc[q * 2 + 0] = add2(zc[q * 2 + 0], m.x);
                zc[q * 2 + 1] = add2(zc[q * 2 + 1], m.y);
            }
        }
        float q = 0.0f;
        const ulonglong2* P2 =
            reinterpret_cast<const ulonglong2*>(&s_P[c * NDIM * NDIM]);
#pragma unroll
        for (int i = 0; i < NDIM; i++) {
            const int nq = i / 4 + 1;
            u64 acc;
            {
                ulonglong2 p = P2[i * 4 + 0];
                acc = mul2(p.x, zc[0]);
                acc = fma2(p.y, zc[1], acc);
            }
#pragma unroll
            for (int w = 1; w < 4; w++) {
                if (w < nq) {
                    ulonglong2 p = P2[i * 4 + w];
                    acc = fma2(p.x, zc[w * 2 + 0], acc);
                    acc = fma2(p.y, zc[w * 2 + 1], acc);
                }
            }
            float sol = hsum2(acc);
            q = fmaf(sol, sol, q);
        }
        v = fmaf(q, -0.5f, s_base[c]) + slj;
    }

    if (isnan(v)) v = __int_as_float(0xff800000);   // -inf, matching reference

    // Stage through smem (pitch 17: conflict-free) -> coalesced global store.
    s_res[lane * 17 + c] = v;
    __syncthreads();

    const int p  = tid >> 4;            // point 0..31
    const int cm = tid & 15;            // comp  0..15
    const int n2 = blockIdx.x * 32 + p;
    if (n2 < N) out[(size_t)n2 * NC + cm] = s_res[p * 17 + cm];
}

// ---------------------------------------------------------------------------
// Launch contract
// ---------------------------------------------------------------------------
extern "C" void kernel_launch(void* const* d_in, const int* in_sizes, int n_in,
                              void* d_out, int out_size) {
    const float* z    = (const float*)d_in[0];   // (N, 16)
    const float* z0   = (const float*)d_in[1];   // (6, 16, 16)
    const float* la   = (const float*)d_in[2];   // (6, 16)
    const float* beta = (const float*)d_in[3];   // (6, 16)
    const float* mean = (const float*)d_in[4];   // (16, 16)
    const float* cov  = (const float*)d_in[5];   // (16, 16, 16)
    float* out = (float*)d_out;                  // (N, 16) float32

    const int N = in_sizes[0] / NDIM;

    setup_kernel<<<1, dim3(NDIM, NC)>>>(la, cov, z0, mean);
    const int blocks = (N + 31) / 32;
    density_kernel<<<blocks, 512>>>(z, z0, beta, mean, out, N);
}